// round 3
// baseline (speedup 1.0000x reference)
#include <cuda_runtime.h>
#include <cuda_bf16.h>
#include <float.h>
#include <math.h>

#define R_ROIS 1000
#define N_CLASS 81
#define N_FG 80
#define IMG_H 600.0f
#define IMG_W 800.0f
#define SCORE_THRESH 0.05f
#define NMS_THRESH 0.5f
#define CAP 1024      // worst-case valid count (<= R_ROIS), pow2 padded
#define REG_CAP 256   // register fast-path capacity (8 slots * 32 lanes)

// Scratch (no cudaMalloc allowed): transposed probs [class][roi]
__device__ float g_probT[N_CLASS * R_ROIS];

// ---------------------------------------------------------------------------
// Kernel A: softmax over classes, one WARP per RoI.
// ---------------------------------------------------------------------------
__global__ __launch_bounds__(256) void softmax_kernel(const float* __restrict__ roi_score) {
    const int warp = (blockIdx.x * blockDim.x + threadIdx.x) >> 5;
    const int lane = threadIdx.x & 31;
    if (warp >= R_ROIS) return;

    const float* sc = roi_score + warp * N_CLASS;
    int c0 = lane, c1 = lane + 32, c2 = lane + 64;
    float s0 = sc[c0];
    float s1 = (c1 < N_CLASS) ? sc[c1] : -FLT_MAX;
    float s2 = (c2 < N_CLASS) ? sc[c2] : -FLT_MAX;

    float m = fmaxf(s0, fmaxf(s1, s2));
#pragma unroll
    for (int o = 16; o > 0; o >>= 1) m = fmaxf(m, __shfl_xor_sync(0xffffffffu, m, o));

    float e0 = expf(s0 - m);
    float e1 = (c1 < N_CLASS) ? expf(s1 - m) : 0.0f;
    float e2 = (c2 < N_CLASS) ? expf(s2 - m) : 0.0f;
    float sum = e0 + e1 + e2;
#pragma unroll
    for (int o = 16; o > 0; o >>= 1) sum += __shfl_xor_sync(0xffffffffu, sum, o);
    float inv = 1.0f / sum;

    g_probT[c0 * R_ROIS + warp] = e0 * inv;
    if (c1 < N_CLASS) g_probT[c1 * R_ROIS + warp] = e1 * inv;
    if (c2 < N_CLASS) g_probT[c2 * R_ROIS + warp] = e2 * inv;
}

// ---------------------------------------------------------------------------
// Warp-0 fast path: decode survivors into registers, rank-sort (no barriers),
// register-resident greedy NMS, write output head rows [0, nv).
// ---------------------------------------------------------------------------
template <int NS>
__device__ __forceinline__ void warp_sort_nms(
    int c, int nv, int lane,
    const float* __restrict__ roi, const float* __restrict__ roi_loc,
    const float* __restrict__ skey, const int* __restrict__ sidx,
    float* ssy0, float* ssx0, float* ssy1, float* ssx1, float* ssar, float* ssk,
    float* __restrict__ out, float* __restrict__ labels)
{
    const unsigned FULL = 0xffffffffu;
    float k_[NS]; int id_[NS];
    float y0_[NS], x0_[NS], y1_[NS], x1_[NS], ar_[NS];

    // load + decode survivors (scattered DRAM, MLP across lanes/slots)
#pragma unroll
    for (int s = 0; s < NS; s++) {
        int t = s * 32 + lane;
        if (t < nv) {
            float kk = skey[t];
            int r = sidx[t];
            k_[s] = kk; id_[s] = r;
            float ry0 = roi[r * 4 + 0], rx0 = roi[r * 4 + 1];
            float ry1 = roi[r * 4 + 2], rx1 = roi[r * 4 + 3];
            float h = ry1 - ry0, w = rx1 - rx0;
            float cy = ry0 + 0.5f * h, cx = rx0 + 0.5f * w;
            const float* lc = roi_loc + r * (N_CLASS * 4) + c * 4;
            float dy = lc[0] * 0.1f, dx = lc[1] * 0.1f;
            float dh = lc[2] * 0.2f, dw = lc[3] * 0.2f;
            float ny = dy * h + cy, nx = dx * w + cx;
            float nh = expf(dh) * h, nw = expf(dw) * w;
            y0_[s] = fminf(fmaxf(ny - 0.5f * nh, 0.0f), IMG_H);
            x0_[s] = fminf(fmaxf(nx - 0.5f * nw, 0.0f), IMG_W);
            y1_[s] = fminf(fmaxf(ny + 0.5f * nh, 0.0f), IMG_H);
            x1_[s] = fminf(fmaxf(nx + 0.5f * nw, 0.0f), IMG_W);
            ar_[s] = (y1_[s] - y0_[s]) * (x1_[s] - x0_[s]);
        } else {
            k_[s] = -FLT_MAX; id_[s] = 0x7fffffff;
            y0_[s] = x0_[s] = y1_[s] = x1_[s] = ar_[s] = 0.0f;
        }
    }

    // rank = #items strictly before me under (score desc, idx asc).
    // Strict total order (idx distinct) -> permutation; identical to stable
    // argsort(-score) regardless of compaction order.
    int rk[NS];
#pragma unroll
    for (int s = 0; s < NS; s++) rk[s] = 0;
#pragma unroll
    for (int sm = 0; sm < NS; sm++) {
        if (sm * 32 >= nv) break;
        float ks = k_[sm]; int is = id_[sm];
        int mmax = nv - sm * 32; if (mmax > 32) mmax = 32;
        for (int lm = 0; lm < mmax; lm++) {
            float km = __shfl_sync(FULL, ks, lm);
            int   im = __shfl_sync(FULL, is, lm);
#pragma unroll
            for (int s = 0; s < NS; s++) {
                bool bef = (km > k_[s]) || (km == k_[s] && im < id_[s]);
                rk[s] += bef ? 1 : 0;
            }
        }
    }

    // scatter into sorted shared arrays, reload sorted into registers
#pragma unroll
    for (int s = 0; s < NS; s++) {
        int t = s * 32 + lane;
        if (t < nv) {
            int p = rk[s];
            ssy0[p] = y0_[s]; ssx0[p] = x0_[s];
            ssy1[p] = y1_[s]; ssx1[p] = x1_[s];
            ssar[p] = ar_[s]; ssk[p]  = k_[s];
        }
    }
    __syncwarp();
#pragma unroll
    for (int s = 0; s < NS; s++) {
        int t = s * 32 + lane;
        if (t < nv) {
            y0_[s] = ssy0[t]; x0_[s] = ssx0[t];
            y1_[s] = ssy1[t]; x1_[s] = ssx1[t];
            ar_[s] = ssar[t]; k_[s]  = ssk[t];
        }
    }

    unsigned keep = 0;
#pragma unroll
    for (int s = 0; s < NS; s++)
        if (s * 32 + lane < nv) keep |= (1u << s);

    // greedy NMS: serial over i, parallel over register-resident j
#pragma unroll 1
    for (int i = 0; i < nv; i++) {
        // broadcast loads (uniform address) issue independent of keep chain
        float iy0 = ssy0[i], ix0 = ssx0[i];
        float iy1 = ssy1[i], ix1 = ssx1[i];
        float iar = ssar[i];
        unsigned km = __shfl_sync(FULL, keep, i & 31);
        if (km & (1u << (i >> 5))) {
#pragma unroll
            for (int s = 0; s < NS; s++) {
                int j = s * 32 + lane;
                if (j > i && (keep & (1u << s))) {
                    float ty = fmaxf(iy0, y0_[s]);
                    float tx = fmaxf(ix0, x0_[s]);
                    float by = fminf(iy1, y1_[s]);
                    float bx = fminf(ix1, x1_[s]);
                    float inter = fmaxf(by - ty, 0.0f) * fmaxf(bx - tx, 0.0f);
                    float iou = inter / (iar + ar_[s] - inter + 1e-9f);
                    if (iou > NMS_THRESH) keep &= ~(1u << s);
                }
            }
        }
    }

    // head output rows [0, nv)
    float* oc = out + (size_t)(c - 1) * R_ROIS * 5;
#pragma unroll
    for (int s = 0; s < NS; s++) {
        int t = s * 32 + lane;
        if (t < nv) {
            bool kp = (keep >> s) & 1u;
            oc[t * 5 + 0] = kp ? y0_[s] : 0.0f;
            oc[t * 5 + 1] = kp ? x0_[s] : 0.0f;
            oc[t * 5 + 2] = kp ? y1_[s] : 0.0f;
            oc[t * 5 + 3] = kp ? x1_[s] : 0.0f;
            oc[t * 5 + 4] = kp ? k_[s]  : 0.0f;
            if (labels)
                labels[(size_t)(c - 1) * R_ROIS + t] = kp ? (float)(c - 1) : -1.0f;
        }
    }
}

// ---------------------------------------------------------------------------
// Kernel B: one CTA per foreground class.
// ---------------------------------------------------------------------------
__global__ __launch_bounds__(256) void nms_kernel(const float* __restrict__ roi,
                                                  const float* __restrict__ roi_loc,
                                                  float* __restrict__ out,
                                                  float* __restrict__ labels) {
    const int c = blockIdx.x + 1;     // class 1..80
    const int tid = threadIdx.x;
    const int lane = tid & 31;
    const int warp = tid >> 5;
    const int NT = 256;

    __shared__ float skey[CAP];
    __shared__ int   sidx[CAP];
    __shared__ int   s_cnt;
    // fast-path sorted arrays
    __shared__ float ssy0[REG_CAP], ssx0[REG_CAP], ssy1[REG_CAP], ssx1[REG_CAP];
    __shared__ float ssar[REG_CAP], ssk[REG_CAP];
    // legacy path
    __shared__ float sb[CAP * 4];
    __shared__ float sarea[CAP];
    __shared__ unsigned char skeep[CAP];

    if (tid == 0) s_cnt = 0;
    __syncthreads();

    // compaction (order arbitrary: sort is a strict total order)
    const float* probc = g_probT + c * R_ROIS;
#pragma unroll 1
    for (int r = tid; r < R_ROIS; r += NT) {
        float p = probc[r];
        if (p > SCORE_THRESH) {
            int pos = atomicAdd(&s_cnt, 1);
            skey[pos] = p;
            sidx[pos] = r;
        }
    }
    __syncthreads();
    const int nv = s_cnt;

    if (nv <= REG_CAP) {
        if (warp == 0) {
            switch ((nv + 31) >> 5) {
                case 0: break;
                case 1: warp_sort_nms<1>(c, nv, lane, roi, roi_loc, skey, sidx,
                                         ssy0, ssx0, ssy1, ssx1, ssar, ssk, out, labels); break;
                case 2: warp_sort_nms<2>(c, nv, lane, roi, roi_loc, skey, sidx,
                                         ssy0, ssx0, ssy1, ssx1, ssar, ssk, out, labels); break;
                case 3:
                case 4: warp_sort_nms<4>(c, nv, lane, roi, roi_loc, skey, sidx,
                                         ssy0, ssx0, ssy1, ssx1, ssar, ssk, out, labels); break;
                default: warp_sort_nms<8>(c, nv, lane, roi, roi_loc, skey, sidx,
                                          ssy0, ssx0, ssy1, ssx1, ssar, ssk, out, labels); break;
            }
        } else {
            // warps 1-7: write tail rows [nv, R) (bulk of stores) in parallel
            float* oc = out + (size_t)(c - 1) * R_ROIS * 5;
            int base = tid - 32;               // 0..223
#pragma unroll 1
            for (int r = nv + base; r < R_ROIS; r += (NT - 32)) {
                oc[r * 5 + 0] = 0.0f;
                oc[r * 5 + 1] = 0.0f;
                oc[r * 5 + 2] = 0.0f;
                oc[r * 5 + 3] = 0.0f;
                oc[r * 5 + 4] = 0.0f;
                if (labels)
                    labels[(size_t)(c - 1) * R_ROIS + r] = -1.0f;
            }
        }
        return;
    }

    // ---------------- legacy path (nv > REG_CAP; uniform branch) ----------
    int P = 1;
    while (P < nv) P <<= 1;
    for (int i = nv + tid; i < P; i += NT) { skey[i] = -FLT_MAX; sidx[i] = 0x7fffffff; }
    __syncthreads();
    for (int k = 2; k <= P; k <<= 1) {
        for (int j = k >> 1; j > 0; j >>= 1) {
            for (int i = tid; i < P; i += NT) {
                int ixj = i ^ j;
                if (ixj > i) {
                    float a = skey[i],  b = skey[ixj];
                    int   ia = sidx[i], ib = sidx[ixj];
                    bool desc = ((i & k) == 0);
                    bool before_ba = (b > a) || (b == a && ib < ia);
                    bool before_ab = (a > b) || (a == b && ia < ib);
                    if (desc ? before_ba : before_ab) {
                        skey[i] = b;  skey[ixj] = a;
                        sidx[i] = ib; sidx[ixj] = ia;
                    }
                }
            }
            __syncthreads();
        }
    }

#pragma unroll 1
    for (int kk = tid; kk < nv; kk += NT) {
        int r = sidx[kk];
        float y0 = roi[r * 4 + 0], x0 = roi[r * 4 + 1];
        float y1 = roi[r * 4 + 2], x1 = roi[r * 4 + 3];
        float h = y1 - y0, w = x1 - x0;
        float cy = y0 + 0.5f * h, cx = x0 + 0.5f * w;
        const float* lc = roi_loc + r * (N_CLASS * 4) + c * 4;
        float dy = lc[0] * 0.1f, dx = lc[1] * 0.1f;
        float dh = lc[2] * 0.2f, dw = lc[3] * 0.2f;
        float ny = dy * h + cy, nx = dx * w + cx;
        float nh = expf(dh) * h, nw = expf(dw) * w;
        float by0 = fminf(fmaxf(ny - 0.5f * nh, 0.0f), IMG_H);
        float bx0 = fminf(fmaxf(nx - 0.5f * nw, 0.0f), IMG_W);
        float by1 = fminf(fmaxf(ny + 0.5f * nh, 0.0f), IMG_H);
        float bx1 = fminf(fmaxf(nx + 0.5f * nw, 0.0f), IMG_W);
        sb[kk * 4 + 0] = by0; sb[kk * 4 + 1] = bx0;
        sb[kk * 4 + 2] = by1; sb[kk * 4 + 3] = bx1;
        sarea[kk] = (by1 - by0) * (bx1 - bx0);
        skeep[kk] = 1;
    }
    __syncthreads();

    if (tid < 32) {
#pragma unroll 1
        for (int i = 0; i < nv; i++) {
            if (skeep[i]) {
                float iy0 = sb[i * 4 + 0], ix0 = sb[i * 4 + 1];
                float iy1 = sb[i * 4 + 2], ix1 = sb[i * 4 + 3];
                float iar = sarea[i];
#pragma unroll 1
                for (int jj = i + 1 + tid; jj < nv; jj += 32) {
                    if (skeep[jj]) {
                        float ty = fmaxf(iy0, sb[jj * 4 + 0]);
                        float tx = fmaxf(ix0, sb[jj * 4 + 1]);
                        float by = fminf(iy1, sb[jj * 4 + 2]);
                        float bx = fminf(ix1, sb[jj * 4 + 3]);
                        float inter = fmaxf(by - ty, 0.0f) * fmaxf(bx - tx, 0.0f);
                        float iou = inter / (iar + sarea[jj] - inter + 1e-9f);
                        if (iou > NMS_THRESH) skeep[jj] = 0;
                    }
                }
            }
            __syncwarp();
        }
    }
    __syncthreads();

    float* oc = out + (size_t)(c - 1) * R_ROIS * 5;
#pragma unroll 1
    for (int r = tid; r < R_ROIS; r += NT) {
        bool kp = (r < nv) && skeep[r];
        oc[r * 5 + 0] = kp ? sb[r * 4 + 0] : 0.0f;
        oc[r * 5 + 1] = kp ? sb[r * 4 + 1] : 0.0f;
        oc[r * 5 + 2] = kp ? sb[r * 4 + 2] : 0.0f;
        oc[r * 5 + 3] = kp ? sb[r * 4 + 3] : 0.0f;
        oc[r * 5 + 4] = kp ? skey[r]       : 0.0f;
        if (labels)
            labels[(size_t)(c - 1) * R_ROIS + r] = kp ? (float)(c - 1) : -1.0f;
    }
}

extern "C" void kernel_launch(void* const* d_in, const int* in_sizes, int n_in,
                              void* d_out, int out_size) {
    const float* roi       = (const float*)d_in[0];  // [1000,4]
    const float* roi_loc   = (const float*)d_in[1];  // [1000,324]
    const float* roi_score = (const float*)d_in[2];  // [1000,81]

    float* out = (float*)d_out;
    const int out_elems   = N_FG * R_ROIS * 5;  // 400000
    const int label_elems = N_FG * R_ROIS;      // 80000
    float* labels = (out_size >= out_elems + label_elems) ? (out + out_elems)
                                                          : nullptr;

    softmax_kernel<<<(R_ROIS * 32 + 255) / 256, 256>>>(roi_score);
    nms_kernel<<<N_FG, 256>>>(roi, roi_loc, out, labels);
}